// round 11
// baseline (speedup 1.0000x reference)
#include <cuda_runtime.h>
#include <cuda_bf16.h>
#include <cstdint>

// Round 11: fused scan + TWO free-running producer warps with 4-way-ILP HMMA.
// 128 CTAs x 320 threads:
//   threads [0,256): scan (REG_K=80 reg rows + SMK=48 smem rows of R, FFMA2
//                    mainloop, shuffle epilogue, named barrier 1)
//   threads [256,320): 2 producer warps; warp p computes n-cols [p*256,+256)
//                    of pre = x@W^T (bf16 3-term HMMA, 4 concurrent acc
//                    chains), publishes progress flag[p].

#define BB 256
#define SS 2048
#define II 64
#define HH 128
#define GG 512
#define NCTA 128
#define NTHR 320

#define REG_K 80
#define SMK   48
#define PTS  (SMK * 2 + 4)          // 100 floats; conflict-free LDS.128 pattern
#define SW_FLOATS (256 * PTS)
#define HB_FLOATS (2 * 2 * HH)
#define SCAN_SMEM_BYTES ((SW_FLOATS + HB_FLOATS + 8) * 4)

typedef unsigned long long u64;

__device__ float g_pre[(long long)BB * SS * GG];          // 1 GB scratch
__device__ __align__(16) unsigned g_whf[GG * 4 * 8];      // W hi, fragment-major
__device__ __align__(16) unsigned g_wlf[GG * 4 * 8];      // W lo residual

__device__ __forceinline__ u64 ffma2(u64 a, u64 b, u64 c) {
    u64 d;
    asm("fma.rn.f32x2 %0, %1, %2, %3;" : "=l"(d) : "l"(a), "l"(b), "l"(c));
    return d;
}
__device__ __forceinline__ u64 packf2(float lo, float hi) {
    u64 r;
    asm("mov.b64 %0, {%1, %2};" : "=l"(r) : "f"(lo), "f"(hi));
    return r;
}
__device__ __forceinline__ float2 unpackf2(u64 v) {
    float2 r;
    asm("mov.b64 {%0, %1}, %2;" : "=f"(r.x), "=f"(r.y) : "l"(v));
    return r;
}
__device__ __forceinline__ float fast_tanh(float x) {
    float xc = fminf(fmaxf(x, -12.0f), 12.0f);
    float e  = __expf(2.0f * xc);
    return __fdividef(e - 1.0f, e + 1.0f);
}
__device__ __forceinline__ unsigned pack_bf16_hi(float a, float b) {
    __nv_bfloat16 ah = __float2bfloat16(a), bh = __float2bfloat16(b);
    return (unsigned)__bfloat16_as_ushort(ah) | ((unsigned)__bfloat16_as_ushort(bh) << 16);
}
__device__ __forceinline__ unsigned pack_bf16_lo(float a, float b) {
    __nv_bfloat16 ah = __float2bfloat16(a), bh = __float2bfloat16(b);
    __nv_bfloat16 al = __float2bfloat16(a - __bfloat162float(ah));
    __nv_bfloat16 bl = __float2bfloat16(b - __bfloat162float(bh));
    return (unsigned)__bfloat16_as_ushort(al) | ((unsigned)__bfloat16_as_ushort(bl) << 16);
}
__device__ __forceinline__ void mma16816(float* c, const unsigned* a,
                                         unsigned b0, unsigned b1) {
    asm volatile(
        "mma.sync.aligned.m16n8k16.row.col.f32.bf16.bf16.f32 "
        "{%0,%1,%2,%3}, {%4,%5,%6,%7}, {%8,%9}, {%0,%1,%2,%3};"
        : "+f"(c[0]), "+f"(c[1]), "+f"(c[2]), "+f"(c[3])
        : "r"(a[0]), "r"(a[1]), "r"(a[2]), "r"(a[3]), "r"(b0), "r"(b1));
}

// prep: W fp32 -> bf16 hi/lo, fragment-major: g_whf[(n*4+tig)*8 + ks*2 + j],
// value = pack(W[n][2u], W[n][2u+1]), u = ks*8 + tig + 4*j
__global__ void prep_w_kernel(const float* __restrict__ Wm) {
    int i = blockIdx.x * 256 + threadIdx.x;   // 8192 = 512n * 4tig * 4ks
    int n = i >> 4, tig = (i >> 2) & 3, ks = i & 3;
#pragma unroll
    for (int j = 0; j < 2; j++) {
        int u = ks * 8 + tig + 4 * j;
        float a = Wm[n * II + 2 * u], b = Wm[n * II + 2 * u + 1];
        int o = (n * 4 + tig) * 8 + ks * 2 + j;
        g_whf[o] = pack_bf16_hi(a, b);
        g_wlf[o] = pack_bf16_lo(a, b);
    }
}

// ---------------------------------------------------------------------------
// Producer: warp computes a half-tile (2 rows x 8 steps x 256 n-cols) per
// s-tile, in 8 groups of 4 n-tiles with 4 independent accumulator chains.
// ---------------------------------------------------------------------------
struct AFrag { unsigned h[4][4]; unsigned l[4][4]; };

__device__ __forceinline__ void prod_load_A(AFrag& A, const float* __restrict__ xg,
                                            int b0, int sbase, int gid, int tig) {
    const float* x0 = xg + ((long long)b0 * SS + sbase + gid) * II;
    const float* x1 = xg + ((long long)(b0 + 1) * SS + sbase + gid) * II;
#pragma unroll
    for (int ks = 0; ks < 4; ks++) {
        int k = 16 * ks + 2 * tig;
        float2 v0 = __ldg((const float2*)(x0 + k));
        float2 v1 = __ldg((const float2*)(x1 + k));
        float2 v2 = __ldg((const float2*)(x0 + k + 8));
        float2 v3 = __ldg((const float2*)(x1 + k + 8));
        A.h[ks][0] = pack_bf16_hi(v0.x, v0.y);  A.l[ks][0] = pack_bf16_lo(v0.x, v0.y);
        A.h[ks][1] = pack_bf16_hi(v1.x, v1.y);  A.l[ks][1] = pack_bf16_lo(v1.x, v1.y);
        A.h[ks][2] = pack_bf16_hi(v2.x, v2.y);  A.l[ks][2] = pack_bf16_lo(v2.x, v2.y);
        A.h[ks][3] = pack_bf16_hi(v3.x, v3.y);  A.l[ks][3] = pack_bf16_lo(v3.x, v3.y);
    }
}

__device__ __forceinline__ void prod_half_tile(const AFrag& A, float* pre,
                                               int b0, int sbase, int gid,
                                               int tig, int nt0) {
    long long s = sbase + gid;
    float* o0 = pre + ((long long)b0 * SS + s) * GG + tig * 2;
    float* o1 = pre + ((long long)(b0 + 1) * SS + s) * GG + tig * 2;
#pragma unroll 1
    for (int g = 0; g < 8; g++) {
        int ntb = nt0 + g * 4;
        uint4 H[8], L[8];                 // 4 n-tiles x (2 hi + 2 lo) uint4
#pragma unroll
        for (int j = 0; j < 4; j++) {
            int n = (ntb + j) * 8 + gid;
            const uint4* whp = (const uint4*)(g_whf + (n * 4 + tig) * 8);
            const uint4* wlp = (const uint4*)(g_wlf + (n * 4 + tig) * 8);
            H[j * 2]     = __ldg(whp);
            H[j * 2 + 1] = __ldg(whp + 1);
            L[j * 2]     = __ldg(wlp);
            L[j * 2 + 1] = __ldg(wlp + 1);
        }
        float acc[4][4];
#pragma unroll
        for (int j = 0; j < 4; j++)
#pragma unroll
            for (int e = 0; e < 4; e++) acc[j][e] = 0.0f;

#pragma unroll
        for (int ks = 0; ks < 4; ks++) {
#pragma unroll
            for (int j = 0; j < 4; j++) {        // 4 independent chains
                const unsigned* hp = (const unsigned*)&H[j * 2];
                const unsigned* lp = (const unsigned*)&L[j * 2];
                unsigned bh0 = hp[ks * 2], bh1 = hp[ks * 2 + 1];
                unsigned bl0 = lp[ks * 2], bl1 = lp[ks * 2 + 1];
                mma16816(acc[j], A.h[ks], bh0, bh1);
                mma16816(acc[j], A.l[ks], bh0, bh1);
                mma16816(acc[j], A.h[ks], bl0, bl1);
            }
        }
#pragma unroll
        for (int j = 0; j < 4; j++) {
            *(float2*)(o0 + (ntb + j) * 8) = make_float2(acc[j][0], acc[j][1]);
            *(float2*)(o1 + (ntb + j) * 8) = make_float2(acc[j][2], acc[j][3]);
        }
    }
}

// ---------------------------------------------------------------------------
__global__ void __launch_bounds__(NTHR, 1)
slstm_fused_kernel(const float* __restrict__ xg, const float* __restrict__ Rm,
                   const float* __restrict__ bias, float* pre,
                   float* __restrict__ out)
{
    extern __shared__ float smem[];
    float* sW = smem;                                 // [256][PTS]
    float* hb = smem + SW_FLOATS;                     // [2][2][HH]
    volatile int* flags = (volatile int*)(smem + SW_FLOATS + HB_FLOATS);  // [2]

    const int tid = threadIdx.x;
    const int b0  = blockIdx.x * 2;
    const bool is_scan = (tid < 256);

    const int w  = tid >> 5;
    const int l  = tid & 31;
    const int c0 = 16 * l + 2 * (w & 7);
    const int c1 = c0 + 1;

    u64 wp0[REG_K / 2], wp1[REG_K / 2];
    float bg0 = 0.f, bg1 = 0.f;

    if (tid == 0) { flags[0] = 0; flags[1] = 0; }

    if (is_scan) {
#pragma unroll
        for (int j = 0; j < REG_K / 2; j++) {
            wp0[j] = packf2(Rm[(2 * j) * GG + c0], Rm[(2 * j + 1) * GG + c0]);
            wp1[j] = packf2(Rm[(2 * j) * GG + c1], Rm[(2 * j + 1) * GG + c1]);
        }
        float* slab = sW + tid * PTS;
#pragma unroll
        for (int kc = 0; kc < SMK; kc += 4) {
            int k = REG_K + kc;
            slab[kc * 2 + 0] = Rm[(k + 0) * GG + c0];
            slab[kc * 2 + 1] = Rm[(k + 1) * GG + c0];
            slab[kc * 2 + 2] = Rm[(k + 0) * GG + c1];
            slab[kc * 2 + 3] = Rm[(k + 1) * GG + c1];
            slab[kc * 2 + 4] = Rm[(k + 2) * GG + c0];
            slab[kc * 2 + 5] = Rm[(k + 3) * GG + c0];
            slab[kc * 2 + 6] = Rm[(k + 2) * GG + c1];
            slab[kc * 2 + 7] = Rm[(k + 3) * GG + c1];
        }
        bg0 = bias[c0];
        bg1 = bias[c1];
        hb[tid] = 0.0f;
        hb[tid + 256] = 0.0f;
    }
    __syncthreads();     // the ONLY full-block barrier

    if (!is_scan) {
        // ---------------- free-running producers (2 warps) ----------------
        const int pw   = (tid - 256) >> 5;            // 0 or 1
        const int ptid = tid & 31;
        const int gid  = ptid >> 2;
        const int tig  = ptid & 3;
        const int nt0  = pw * 32;
        AFrag A;
#pragma unroll 1
        for (int tile = 0; tile < SS / 8; tile++) {
            prod_load_A(A, xg, b0, tile * 8, gid, tig);
            prod_half_tile(A, pre, b0, tile * 8, gid, tig, nt0);
            __threadfence_block();                    // order STG before flag
            if (ptid == 0) flags[pw] = (tile + 1) * 8;
        }
        return;
    }

    // ---------------- scan ----------------
    const float* pr0 = pre + (long long)(b0)     * SS * GG;
    const float* pr1 = pre + (long long)(b0 + 1) * SS * GG;

    int seen = 0;
#define WAITS(need) do { int _n = (need); if (seen < _n) {                       \
        for (;;) { int _f0 = flags[0]; int _f1 = flags[1];                       \
                   seen = _f0 < _f1 ? _f0 : _f1; if (seen >= _n) break; }        \
        __threadfence_block(); } } while (0)

    WAITS(2);
    float2 p0 = *(const float2*)(pr0 + c0);
    float2 p1 = *(const float2*)(pr1 + c0);

    const int my_row = (l >> 4) & 1;
    const int my_hid = 16 * (l & 7) + 2 * (w & 7) + ((l >> 3) & 1);
    float c_ = 0.0f, n_ = 0.0f, m_ = 0.0f;

    const bool lo16 = (l < 16);
    const bool b3   = ((l >> 3) & 1) != 0;
    const float* sWg = sW + tid * PTS;

#pragma unroll 1
    for (int step = 0; step < SS; step++) {
        const float* h0 = hb + (step & 1) * 256;
        const float* h1 = h0 + HH;
        float* hn = hb + ((step + 1) & 1) * 256;

        float2 q0 = make_float2(0.f, 0.f), q1 = make_float2(0.f, 0.f);
        if (step + 1 < SS) {
            WAITS(step + 2);
            long long off = (long long)(step + 1) * GG;
            q0 = *(const float2*)(pr0 + off + c0);
            q1 = *(const float2*)(pr1 + off + c0);
        }

        u64 a00 = 0, a10 = 0, a01 = 0, a11 = 0;

#pragma unroll
        for (int k = 0; k < REG_K; k += 4) {
            ulonglong2 hp0 = *(const ulonglong2*)(h0 + k);
            ulonglong2 hp1 = *(const ulonglong2*)(h1 + k);
            int j = k / 2;
            a00 = ffma2(hp0.x, wp0[j],     a00);
            a10 = ffma2(hp0.x, wp1[j],     a10);
            a01 = ffma2(hp1.x, wp0[j],     a01);
            a11 = ffma2(hp1.x, wp1[j],     a11);
            a00 = ffma2(hp0.y, wp0[j + 1], a00);
            a10 = ffma2(hp0.y, wp1[j + 1], a10);
            a01 = ffma2(hp1.y, wp0[j + 1], a01);
            a11 = ffma2(hp1.y, wp1[j + 1], a11);
        }
#pragma unroll
        for (int k = 0; k < SMK; k += 4) {
            ulonglong2 wv0 = *(const ulonglong2*)(sWg + k * 2);
            ulonglong2 wv1 = *(const ulonglong2*)(sWg + k * 2 + 4);
            ulonglong2 hp0 = *(const ulonglong2*)(h0 + REG_K + k);
            ulonglong2 hp1 = *(const ulonglong2*)(h1 + REG_K + k);
            a00 = ffma2(hp0.x, wv0.x, a00);
            a10 = ffma2(hp0.x, wv0.y, a10);
            a01 = ffma2(hp1.x, wv0.x, a01);
            a11 = ffma2(hp1.x, wv0.y, a11);
            a00 = ffma2(hp0.y, wv1.x, a00);
            a10 = ffma2(hp0.y, wv1.y, a10);
            a01 = ffma2(hp1.y, wv1.x, a01);
            a11 = ffma2(hp1.y, wv1.y, a11);
        }

        float2 t0 = unpackf2(a00), t1 = unpackf2(a10);
        float2 t2 = unpackf2(a01), t3 = unpackf2(a11);
        float aa = t0.x + t0.y + p0.x + bg0;
        float bb = t1.x + t1.y + p0.y + bg1;
        float cc = t2.x + t2.y + p1.x + bg0;
        float dd = t3.x + t3.y + p1.y + bg1;

        // warp-local gate transpose (4 shuffles)
        float u1 = lo16 ? cc : aa;
        float u2 = lo16 ? dd : bb;
        float r1v = __shfl_xor_sync(0xFFFFFFFFu, u1, 16);
        float r2v = __shfl_xor_sync(0xFFFFFFFFu, u2, 16);
        float Ag = lo16 ? aa : r1v;
        float Bg = lo16 ? bb : r2v;
        float Cg = lo16 ? r1v : cc;
        float Dg = lo16 ? r2v : dd;
        float s1in = b3 ? Ag : Bg;
        float s2in = b3 ? Cg : Dg;
        float e1 = __shfl_xor_sync(0xFFFFFFFFu, s1in, 8);
        float e2 = __shfl_xor_sync(0xFFFFFFFFu, s2in, 8);
        float iv = b3 ? e1 : Ag;
        float fv = b3 ? Bg : e1;
        float ov = b3 ? e2 : Cg;
        float zv = b3 ? Dg : e2;

        float tz = fast_tanh(zv);
        float so = __fdividef(1.0f, 1.0f + __expf(-ov));
        float lf = fminf(fv, 0.0f) - __logf(1.0f + __expf(-fabsf(fv)));
        float mn = fmaxf(lf + m_, iv);
        float ip = __expf(iv - mn);
        float fp = __expf(lf + m_ - mn);
        c_ = fp * c_ + ip * tz;
        n_ = fp * n_ + ip;
        m_ = mn;
        float hv = so * fast_tanh(__fdividef(c_, n_));

        hn[my_row * HH + my_hid] = hv;
        out[((long long)(b0 + my_row) * SS + step) * HH + my_hid] = hv;

        p0 = q0; p1 = q1;
        asm volatile("bar.sync 1, 256;" ::: "memory");   // scan warps only
    }
}

extern "C" void kernel_launch(void* const* d_in, const int* in_sizes, int n_in,
                              void* d_out, int out_size)
{
    const float* xg = (const float*)d_in[0];
    const float* Wm = (const float*)d_in[1];
    const float* Rm = (const float*)d_in[2];
    const float* bv = (const float*)d_in[3];
    if (n_in >= 3 && in_sizes[1] == HH * GG && in_sizes[2] == GG * II) {
        const float* t = Wm; Wm = Rm; Rm = t;
    }
    float* out = (float*)d_out;

    float* pre = nullptr;
    cudaGetSymbolAddress((void**)&pre, g_pre);

    cudaFuncSetAttribute(slstm_fused_kernel,
                         cudaFuncAttributeMaxDynamicSharedMemorySize, SCAN_SMEM_BYTES);

    prep_w_kernel<<<32, 256>>>(Wm);
    slstm_fused_kernel<<<NCTA, NTHR, SCAN_SMEM_BYTES>>>(xg, Rm, bv, pre, out);
}

// round 12
// speedup vs baseline: 1.0003x; 1.0003x over previous
#include <cuda_runtime.h>
#include <cuda_bf16.h>
#include <cstdint>

// Round 11: fused scan + TWO free-running producer warps with 4-way-ILP HMMA.
// 128 CTAs x 320 threads:
//   threads [0,256): scan (REG_K=80 reg rows + SMK=48 smem rows of R, FFMA2
//                    mainloop, shuffle epilogue, named barrier 1)
//   threads [256,320): 2 producer warps; warp p computes n-cols [p*256,+256)
//                    of pre = x@W^T (bf16 3-term HMMA, 4 concurrent acc
//                    chains), publishes progress flag[p].

#define BB 256
#define SS 2048
#define II 64
#define HH 128
#define GG 512
#define NCTA 128
#define NTHR 320

#define REG_K 80
#define SMK   48
#define PTS  (SMK * 2 + 4)          // 100 floats; conflict-free LDS.128 pattern
#define SW_FLOATS (256 * PTS)
#define HB_FLOATS (2 * 2 * HH)
#define SCAN_SMEM_BYTES ((SW_FLOATS + HB_FLOATS + 8) * 4)

typedef unsigned long long u64;

__device__ float g_pre[(long long)BB * SS * GG];          // 1 GB scratch
__device__ __align__(16) unsigned g_whf[GG * 4 * 8];      // W hi, fragment-major
__device__ __align__(16) unsigned g_wlf[GG * 4 * 8];      // W lo residual

__device__ __forceinline__ u64 ffma2(u64 a, u64 b, u64 c) {
    u64 d;
    asm("fma.rn.f32x2 %0, %1, %2, %3;" : "=l"(d) : "l"(a), "l"(b), "l"(c));
    return d;
}
__device__ __forceinline__ u64 packf2(float lo, float hi) {
    u64 r;
    asm("mov.b64 %0, {%1, %2};" : "=l"(r) : "f"(lo), "f"(hi));
    return r;
}
__device__ __forceinline__ float2 unpackf2(u64 v) {
    float2 r;
    asm("mov.b64 {%0, %1}, %2;" : "=f"(r.x), "=f"(r.y) : "l"(v));
    return r;
}
__device__ __forceinline__ float fast_tanh(float x) {
    float xc = fminf(fmaxf(x, -12.0f), 12.0f);
    float e  = __expf(2.0f * xc);
    return __fdividef(e - 1.0f, e + 1.0f);
}
__device__ __forceinline__ unsigned pack_bf16_hi(float a, float b) {
    __nv_bfloat16 ah = __float2bfloat16(a), bh = __float2bfloat16(b);
    return (unsigned)__bfloat16_as_ushort(ah) | ((unsigned)__bfloat16_as_ushort(bh) << 16);
}
__device__ __forceinline__ unsigned pack_bf16_lo(float a, float b) {
    __nv_bfloat16 ah = __float2bfloat16(a), bh = __float2bfloat16(b);
    __nv_bfloat16 al = __float2bfloat16(a - __bfloat162float(ah));
    __nv_bfloat16 bl = __float2bfloat16(b - __bfloat162float(bh));
    return (unsigned)__bfloat16_as_ushort(al) | ((unsigned)__bfloat16_as_ushort(bl) << 16);
}
__device__ __forceinline__ void mma16816(float* c, const unsigned* a,
                                         unsigned b0, unsigned b1) {
    asm volatile(
        "mma.sync.aligned.m16n8k16.row.col.f32.bf16.bf16.f32 "
        "{%0,%1,%2,%3}, {%4,%5,%6,%7}, {%8,%9}, {%0,%1,%2,%3};"
        : "+f"(c[0]), "+f"(c[1]), "+f"(c[2]), "+f"(c[3])
        : "r"(a[0]), "r"(a[1]), "r"(a[2]), "r"(a[3]), "r"(b0), "r"(b1));
}

// prep: W fp32 -> bf16 hi/lo, fragment-major: g_whf[(n*4+tig)*8 + ks*2 + j],
// value = pack(W[n][2u], W[n][2u+1]), u = ks*8 + tig + 4*j
__global__ void prep_w_kernel(const float* __restrict__ Wm) {
    int i = blockIdx.x * 256 + threadIdx.x;   // 8192 = 512n * 4tig * 4ks
    int n = i >> 4, tig = (i >> 2) & 3, ks = i & 3;
#pragma unroll
    for (int j = 0; j < 2; j++) {
        int u = ks * 8 + tig + 4 * j;
        float a = Wm[n * II + 2 * u], b = Wm[n * II + 2 * u + 1];
        int o = (n * 4 + tig) * 8 + ks * 2 + j;
        g_whf[o] = pack_bf16_hi(a, b);
        g_wlf[o] = pack_bf16_lo(a, b);
    }
}

// ---------------------------------------------------------------------------
// Producer: warp computes a half-tile (2 rows x 8 steps x 256 n-cols) per
// s-tile, in 8 groups of 4 n-tiles with 4 independent accumulator chains.
// ---------------------------------------------------------------------------
struct AFrag { unsigned h[4][4]; unsigned l[4][4]; };

__device__ __forceinline__ void prod_load_A(AFrag& A, const float* __restrict__ xg,
                                            int b0, int sbase, int gid, int tig) {
    const float* x0 = xg + ((long long)b0 * SS + sbase + gid) * II;
    const float* x1 = xg + ((long long)(b0 + 1) * SS + sbase + gid) * II;
#pragma unroll
    for (int ks = 0; ks < 4; ks++) {
        int k = 16 * ks + 2 * tig;
        float2 v0 = __ldg((const float2*)(x0 + k));
        float2 v1 = __ldg((const float2*)(x1 + k));
        float2 v2 = __ldg((const float2*)(x0 + k + 8));
        float2 v3 = __ldg((const float2*)(x1 + k + 8));
        A.h[ks][0] = pack_bf16_hi(v0.x, v0.y);  A.l[ks][0] = pack_bf16_lo(v0.x, v0.y);
        A.h[ks][1] = pack_bf16_hi(v1.x, v1.y);  A.l[ks][1] = pack_bf16_lo(v1.x, v1.y);
        A.h[ks][2] = pack_bf16_hi(v2.x, v2.y);  A.l[ks][2] = pack_bf16_lo(v2.x, v2.y);
        A.h[ks][3] = pack_bf16_hi(v3.x, v3.y);  A.l[ks][3] = pack_bf16_lo(v3.x, v3.y);
    }
}

__device__ __forceinline__ void prod_half_tile(const AFrag& A, float* pre,
                                               int b0, int sbase, int gid,
                                               int tig, int nt0) {
    long long s = sbase + gid;
    float* o0 = pre + ((long long)b0 * SS + s) * GG + tig * 2;
    float* o1 = pre + ((long long)(b0 + 1) * SS + s) * GG + tig * 2;
#pragma unroll 1
    for (int g = 0; g < 8; g++) {
        int ntb = nt0 + g * 4;
        uint4 H[8], L[8];                 // 4 n-tiles x (2 hi + 2 lo) uint4
#pragma unroll
        for (int j = 0; j < 4; j++) {
            int n = (ntb + j) * 8 + gid;
            const uint4* whp = (const uint4*)(g_whf + (n * 4 + tig) * 8);
            const uint4* wlp = (const uint4*)(g_wlf + (n * 4 + tig) * 8);
            H[j * 2]     = __ldg(whp);
            H[j * 2 + 1] = __ldg(whp + 1);
            L[j * 2]     = __ldg(wlp);
            L[j * 2 + 1] = __ldg(wlp + 1);
        }
        float acc[4][4];
#pragma unroll
        for (int j = 0; j < 4; j++)
#pragma unroll
            for (int e = 0; e < 4; e++) acc[j][e] = 0.0f;

#pragma unroll
        for (int ks = 0; ks < 4; ks++) {
#pragma unroll
            for (int j = 0; j < 4; j++) {        // 4 independent chains
                const unsigned* hp = (const unsigned*)&H[j * 2];
                const unsigned* lp = (const unsigned*)&L[j * 2];
                unsigned bh0 = hp[ks * 2], bh1 = hp[ks * 2 + 1];
                unsigned bl0 = lp[ks * 2], bl1 = lp[ks * 2 + 1];
                mma16816(acc[j], A.h[ks], bh0, bh1);
                mma16816(acc[j], A.l[ks], bh0, bh1);
                mma16816(acc[j], A.h[ks], bl0, bl1);
            }
        }
#pragma unroll
        for (int j = 0; j < 4; j++) {
            *(float2*)(o0 + (ntb + j) * 8) = make_float2(acc[j][0], acc[j][1]);
            *(float2*)(o1 + (ntb + j) * 8) = make_float2(acc[j][2], acc[j][3]);
        }
    }
}

// ---------------------------------------------------------------------------
__global__ void __launch_bounds__(NTHR, 1)
slstm_fused_kernel(const float* __restrict__ xg, const float* __restrict__ Rm,
                   const float* __restrict__ bias, float* pre,
                   float* __restrict__ out)
{
    extern __shared__ float smem[];
    float* sW = smem;                                 // [256][PTS]
    float* hb = smem + SW_FLOATS;                     // [2][2][HH]
    volatile int* flags = (volatile int*)(smem + SW_FLOATS + HB_FLOATS);  // [2]

    const int tid = threadIdx.x;
    const int b0  = blockIdx.x * 2;
    const bool is_scan = (tid < 256);

    const int w  = tid >> 5;
    const int l  = tid & 31;
    const int c0 = 16 * l + 2 * (w & 7);
    const int c1 = c0 + 1;

    u64 wp0[REG_K / 2], wp1[REG_K / 2];
    float bg0 = 0.f, bg1 = 0.f;

    if (tid == 0) { flags[0] = 0; flags[1] = 0; }

    if (is_scan) {
#pragma unroll
        for (int j = 0; j < REG_K / 2; j++) {
            wp0[j] = packf2(Rm[(2 * j) * GG + c0], Rm[(2 * j + 1) * GG + c0]);
            wp1[j] = packf2(Rm[(2 * j) * GG + c1], Rm[(2 * j + 1) * GG + c1]);
        }
        float* slab = sW + tid * PTS;
#pragma unroll
        for (int kc = 0; kc < SMK; kc += 4) {
            int k = REG_K + kc;
            slab[kc * 2 + 0] = Rm[(k + 0) * GG + c0];
            slab[kc * 2 + 1] = Rm[(k + 1) * GG + c0];
            slab[kc * 2 + 2] = Rm[(k + 0) * GG + c1];
            slab[kc * 2 + 3] = Rm[(k + 1) * GG + c1];
            slab[kc * 2 + 4] = Rm[(k + 2) * GG + c0];
            slab[kc * 2 + 5] = Rm[(k + 3) * GG + c0];
            slab[kc * 2 + 6] = Rm[(k + 2) * GG + c1];
            slab[kc * 2 + 7] = Rm[(k + 3) * GG + c1];
        }
        bg0 = bias[c0];
        bg1 = bias[c1];
        hb[tid] = 0.0f;
        hb[tid + 256] = 0.0f;
    }
    __syncthreads();     // the ONLY full-block barrier

    if (!is_scan) {
        // ---------------- free-running producers (2 warps) ----------------
        const int pw   = (tid - 256) >> 5;            // 0 or 1
        const int ptid = tid & 31;
        const int gid  = ptid >> 2;
        const int tig  = ptid & 3;
        const int nt0  = pw * 32;
        AFrag A;
#pragma unroll 1
        for (int tile = 0; tile < SS / 8; tile++) {
            prod_load_A(A, xg, b0, tile * 8, gid, tig);
            prod_half_tile(A, pre, b0, tile * 8, gid, tig, nt0);
            __threadfence_block();                    // order STG before flag
            if (ptid == 0) flags[pw] = (tile + 1) * 8;
        }
        return;
    }

    // ---------------- scan ----------------
    const float* pr0 = pre + (long long)(b0)     * SS * GG;
    const float* pr1 = pre + (long long)(b0 + 1) * SS * GG;

    int seen = 0;
#define WAITS(need) do { int _n = (need); if (seen < _n) {                       \
        for (;;) { int _f0 = flags[0]; int _f1 = flags[1];                       \
                   seen = _f0 < _f1 ? _f0 : _f1; if (seen >= _n) break; }        \
        __threadfence_block(); } } while (0)

    WAITS(2);
    float2 p0 = *(const float2*)(pr0 + c0);
    float2 p1 = *(const float2*)(pr1 + c0);

    const int my_row = (l >> 4) & 1;
    const int my_hid = 16 * (l & 7) + 2 * (w & 7) + ((l >> 3) & 1);
    float c_ = 0.0f, n_ = 0.0f, m_ = 0.0f;

    const bool lo16 = (l < 16);
    const bool b3   = ((l >> 3) & 1) != 0;
    const float* sWg = sW + tid * PTS;

#pragma unroll 1
    for (int step = 0; step < SS; step++) {
        const float* h0 = hb + (step & 1) * 256;
        const float* h1 = h0 + HH;
        float* hn = hb + ((step + 1) & 1) * 256;

        float2 q0 = make_float2(0.f, 0.f), q1 = make_float2(0.f, 0.f);
        if (step + 1 < SS) {
            WAITS(step + 2);
            long long off = (long long)(step + 1) * GG;
            q0 = *(const float2*)(pr0 + off + c0);
            q1 = *(const float2*)(pr1 + off + c0);
        }

        u64 a00 = 0, a10 = 0, a01 = 0, a11 = 0;

#pragma unroll
        for (int k = 0; k < REG_K; k += 4) {
            ulonglong2 hp0 = *(const ulonglong2*)(h0 + k);
            ulonglong2 hp1 = *(const ulonglong2*)(h1 + k);
            int j = k / 2;
            a00 = ffma2(hp0.x, wp0[j],     a00);
            a10 = ffma2(hp0.x, wp1[j],     a10);
            a01 = ffma2(hp1.x, wp0[j],     a01);
            a11 = ffma2(hp1.x, wp1[j],     a11);
            a00 = ffma2(hp0.y, wp0[j + 1], a00);
            a10 = ffma2(hp0.y, wp1[j + 1], a10);
            a01 = ffma2(hp1.y, wp0[j + 1], a01);
            a11 = ffma2(hp1.y, wp1[j + 1], a11);
        }
#pragma unroll
        for (int k = 0; k < SMK; k += 4) {
            ulonglong2 wv0 = *(const ulonglong2*)(sWg + k * 2);
            ulonglong2 wv1 = *(const ulonglong2*)(sWg + k * 2 + 4);
            ulonglong2 hp0 = *(const ulonglong2*)(h0 + REG_K + k);
            ulonglong2 hp1 = *(const ulonglong2*)(h1 + REG_K + k);
            a00 = ffma2(hp0.x, wv0.x, a00);
            a10 = ffma2(hp0.x, wv0.y, a10);
            a01 = ffma2(hp1.x, wv0.x, a01);
            a11 = ffma2(hp1.x, wv0.y, a11);
            a00 = ffma2(hp0.y, wv1.x, a00);
            a10 = ffma2(hp0.y, wv1.y, a10);
            a01 = ffma2(hp1.y, wv1.x, a01);
            a11 = ffma2(hp1.y, wv1.y, a11);
        }

        float2 t0 = unpackf2(a00), t1 = unpackf2(a10);
        float2 t2 = unpackf2(a01), t3 = unpackf2(a11);
        float aa = t0.x + t0.y + p0.x + bg0;
        float bb = t1.x + t1.y + p0.y + bg1;
        float cc = t2.x + t2.y + p1.x + bg0;
        float dd = t3.x + t3.y + p1.y + bg1;

        // warp-local gate transpose (4 shuffles)
        float u1 = lo16 ? cc : aa;
        float u2 = lo16 ? dd : bb;
        float r1v = __shfl_xor_sync(0xFFFFFFFFu, u1, 16);
        float r2v = __shfl_xor_sync(0xFFFFFFFFu, u2, 16);
        float Ag = lo16 ? aa : r1v;
        float Bg = lo16 ? bb : r2v;
        float Cg = lo16 ? r1v : cc;
        float Dg = lo16 ? r2v : dd;
        float s1in = b3 ? Ag : Bg;
        float s2in = b3 ? Cg : Dg;
        float e1 = __shfl_xor_sync(0xFFFFFFFFu, s1in, 8);
        float e2 = __shfl_xor_sync(0xFFFFFFFFu, s2in, 8);
        float iv = b3 ? e1 : Ag;
        float fv = b3 ? Bg : e1;
        float ov = b3 ? e2 : Cg;
        float zv = b3 ? Dg : e2;

        float tz = fast_tanh(zv);
        float so = __fdividef(1.0f, 1.0f + __expf(-ov));
        float lf = fminf(fv, 0.0f) - __logf(1.0f + __expf(-fabsf(fv)));
        float mn = fmaxf(lf + m_, iv);
        float ip = __expf(iv - mn);
        float fp = __expf(lf + m_ - mn);
        c_ = fp * c_ + ip * tz;
        n_ = fp * n_ + ip;
        m_ = mn;
        float hv = so * fast_tanh(__fdividef(c_, n_));

        hn[my_row * HH + my_hid] = hv;
        out[((long long)(b0 + my_row) * SS + step) * HH + my_hid] = hv;

        p0 = q0; p1 = q1;
        asm volatile("bar.sync 1, 256;" ::: "memory");   // scan warps only
    }
}

extern "C" void kernel_launch(void* const* d_in, const int* in_sizes, int n_in,
                              void* d_out, int out_size)
{
    const float* xg = (const float*)d_in[0];
    const float* Wm = (const float*)d_in[1];
    const float* Rm = (const float*)d_in[2];
    const float* bv = (const float*)d_in[3];
    if (n_in >= 3 && in_sizes[1] == HH * GG && in_sizes[2] == GG * II) {
        const float* t = Wm; Wm = Rm; Rm = t;
    }
    float* out = (float*)d_out;

    float* pre = nullptr;
    cudaGetSymbolAddress((void**)&pre, g_pre);

    cudaFuncSetAttribute(slstm_fused_kernel,
                         cudaFuncAttributeMaxDynamicSharedMemorySize, SCAN_SMEM_BYTES);

    prep_w_kernel<<<32, 256>>>(Wm);
    slstm_fused_kernel<<<NCTA, NTHR, SCAN_SMEM_BYTES>>>(xg, Rm, bv, pre, out);
}

// round 13
// speedup vs baseline: 1.8154x; 1.8149x over previous
#include <cuda_runtime.h>
#include <cuda_bf16.h>
#include <cstdint>

// Round 13: CTA-level specialization in ONE kernel.
//   blocks [0,20):    producer CTAs - persistent HMMA GEMM (B resident in smem),
//                     sweep chunk(64 steps) x assigned batch-pairs, publish
//                     per-pair progress flags in global memory.
//   blocks [20,148):  scan CTAs - exact round-7 scan (REG_K=96 + SMK=32,
//                     FFMA2 mainloop, shuffle epilogue, 1 __syncthreads/step),
//                     polling the pair's flag at chunk granularity.
// Grid = 148 CTAs -> single wave on GB300 (152 SMs); producers never wait.

#define BB 256
#define SS 2048
#define II 64
#define HH 128
#define GG 512
#define NPROD 20
#define NSCAN 128
#define NTHR 256
#define CHUNK 64

#define REG_K 96
#define SMK   32
#define PTS  (SMK * 2 + 4)              // 68 floats (proven conflict-free)
#define SW_FLOATS (NTHR * PTS)
#define HB_FLOATS (2 * 2 * HH)

// producer smem (uints): Ah[64*36] Al[64*36] Bh[512*36] Bl[512*36]
#define ARS 36
#define OFF_AH 0
#define OFF_AL (64 * ARS)
#define OFF_BH (2 * 64 * ARS)
#define OFF_BL (OFF_BH + 512 * ARS)
#define PROD_UINTS (OFF_BL + 512 * ARS)
#define SMEM_BYTES (PROD_UINTS * 4)     // 165,888 B > scan's 71,680 B

typedef unsigned long long u64;

__device__ float g_pre[(long long)BB * SS * GG];          // 1 GB scratch
__device__ __align__(16) unsigned g_wh[GG * II / 2];      // W hi bf16 pairs (flat)
__device__ __align__(16) unsigned g_wl[GG * II / 2];      // W lo residual
__device__ volatile int g_flag[NSCAN];                    // per-pair steps done

__device__ __forceinline__ u64 ffma2(u64 a, u64 b, u64 c) {
    u64 d;
    asm("fma.rn.f32x2 %0, %1, %2, %3;" : "=l"(d) : "l"(a), "l"(b), "l"(c));
    return d;
}
__device__ __forceinline__ u64 packf2(float lo, float hi) {
    u64 r;
    asm("mov.b64 %0, {%1, %2};" : "=l"(r) : "f"(lo), "f"(hi));
    return r;
}
__device__ __forceinline__ float2 unpackf2(u64 v) {
    float2 r;
    asm("mov.b64 {%0, %1}, %2;" : "=f"(r.x), "=f"(r.y) : "l"(v));
    return r;
}
__device__ __forceinline__ float fast_tanh(float x) {
    float xc = fminf(fmaxf(x, -12.0f), 12.0f);
    float e  = __expf(2.0f * xc);
    return __fdividef(e - 1.0f, e + 1.0f);
}
__device__ __forceinline__ unsigned pack_bf16_hi(float a, float b) {
    __nv_bfloat16 ah = __float2bfloat16(a), bh = __float2bfloat16(b);
    return (unsigned)__bfloat16_as_ushort(ah) | ((unsigned)__bfloat16_as_ushort(bh) << 16);
}
__device__ __forceinline__ unsigned pack_bf16_lo(float a, float b) {
    __nv_bfloat16 ah = __float2bfloat16(a), bh = __float2bfloat16(b);
    __nv_bfloat16 al = __float2bfloat16(a - __bfloat162float(ah));
    __nv_bfloat16 bl = __float2bfloat16(b - __bfloat162float(bh));
    return (unsigned)__bfloat16_as_ushort(al) | ((unsigned)__bfloat16_as_ushort(bl) << 16);
}
__device__ __forceinline__ void mma16816(float* c, const unsigned* a,
                                         unsigned b0, unsigned b1) {
    asm volatile(
        "mma.sync.aligned.m16n8k16.row.col.f32.bf16.bf16.f32 "
        "{%0,%1,%2,%3}, {%4,%5,%6,%7}, {%8,%9}, {%0,%1,%2,%3};"
        : "+f"(c[0]), "+f"(c[1]), "+f"(c[2]), "+f"(c[3])
        : "r"(a[0]), "r"(a[1]), "r"(a[2]), "r"(a[3]), "r"(b0), "r"(b1));
}

// prep: W -> bf16 hi/lo packed pairs (flat), and zero the progress flags.
__global__ void prep_w_kernel(const float* __restrict__ Wm) {
    int i = blockIdx.x * 256 + threadIdx.x;       // 16384 pairs
    float a = Wm[2 * i], b = Wm[2 * i + 1];
    g_wh[i] = pack_bf16_hi(a, b);
    g_wl[i] = pack_bf16_lo(a, b);
    if (blockIdx.x == 0 && threadIdx.x < NSCAN) g_flag[threadIdx.x] = 0;
}

// ---------------------------------------------------------------------------
// Producer tile: M=64 (rows mbase..mbase+63 of flattened (b*SS+s)), N=512, K=64
// ---------------------------------------------------------------------------
__device__ void prod_tile(unsigned* usm, const float* __restrict__ xg,
                          float* pre, long long mbase) {
    unsigned* Ah = usm + OFF_AH;
    unsigned* Al = usm + OFF_AL;
    unsigned* Bh = usm + OFF_BH;
    unsigned* Bl = usm + OFF_BL;
    const int tid = threadIdx.x;

    __syncthreads();                     // A smem reuse from previous tile
    {
        const float* xt = xg + mbase * II;
#pragma unroll
        for (int j = 0; j < 8; j++) {
            int idx = tid + j * 256;
            int row = idx >> 5, kp = idx & 31;
            float2 v = *(const float2*)(xt + row * II + kp * 2);
            Ah[row * ARS + kp] = pack_bf16_hi(v.x, v.y);
            Al[row * ARS + kp] = pack_bf16_lo(v.x, v.y);
        }
    }
    __syncthreads();

    const int w    = tid >> 5;
    const int lane = tid & 31;
    const int gid  = lane >> 2;
    const int tig  = lane & 3;
    const int mg   = w >> 2;
    const int ng   = w & 3;

    float acc[2][16][4];
#pragma unroll
    for (int mt = 0; mt < 2; mt++)
#pragma unroll
        for (int nc = 0; nc < 16; nc++)
#pragma unroll
            for (int e = 0; e < 4; e++) acc[mt][nc][e] = 0.0f;

#pragma unroll
    for (int ks = 0; ks < 4; ks++) {
        unsigned ah[2][4], al[2][4];
#pragma unroll
        for (int mt = 0; mt < 2; mt++) {
            int r0 = mg * 32 + mt * 16 + gid;
            int ui = ks * 8 + tig;
            ah[mt][0] = Ah[r0 * ARS + ui];
            ah[mt][1] = Ah[(r0 + 8) * ARS + ui];
            ah[mt][2] = Ah[r0 * ARS + ui + 4];
            ah[mt][3] = Ah[(r0 + 8) * ARS + ui + 4];
            al[mt][0] = Al[r0 * ARS + ui];
            al[mt][1] = Al[(r0 + 8) * ARS + ui];
            al[mt][2] = Al[r0 * ARS + ui + 4];
            al[mt][3] = Al[(r0 + 8) * ARS + ui + 4];
        }
#pragma unroll
        for (int nc = 0; nc < 16; nc++) {
            int n  = ng * 128 + nc * 8 + gid;
            int ui = ks * 8 + tig;
            unsigned bh0 = Bh[n * ARS + ui];
            unsigned bh1 = Bh[n * ARS + ui + 4];
            unsigned bl0 = Bl[n * ARS + ui];
            unsigned bl1 = Bl[n * ARS + ui + 4];
#pragma unroll
            for (int mt = 0; mt < 2; mt++) {
                mma16816(acc[mt][nc], ah[mt], bh0, bh1);
                mma16816(acc[mt][nc], al[mt], bh0, bh1);
                mma16816(acc[mt][nc], ah[mt], bl0, bl1);
            }
        }
    }
#pragma unroll
    for (int mt = 0; mt < 2; mt++) {
#pragma unroll
        for (int nc = 0; nc < 16; nc++) {
            long long m = mbase + mg * 32 + mt * 16 + gid;
            int n = ng * 128 + nc * 8 + tig * 2;
            *(float2*)(pre + m * GG + n)       = make_float2(acc[mt][nc][0], acc[mt][nc][1]);
            *(float2*)(pre + (m + 8) * GG + n) = make_float2(acc[mt][nc][2], acc[mt][nc][3]);
        }
    }
}

// ---------------------------------------------------------------------------
__global__ void __launch_bounds__(NTHR, 1)
slstm_combined_kernel(const float* __restrict__ xg, const float* __restrict__ Rm,
                      const float* __restrict__ bias, float* pre,
                      float* __restrict__ out)
{
    extern __shared__ float smem[];
    const int tid = threadIdx.x;

    if (blockIdx.x < NPROD) {
        // ================= producer CTA =================
        unsigned* usm = (unsigned*)smem;
        unsigned* Bh = usm + OFF_BH;
        unsigned* Bl = usm + OFF_BL;
        // load B (full W, bf16 hi/lo) once
#pragma unroll
        for (int j = 0; j < 16; j++) {
            int idx = tid + j * 256;
            int n = idx >> 3, kq = idx & 7;
            uint4 hv = ((const uint4*)g_wh)[idx];
            uint4 lv = ((const uint4*)g_wl)[idx];
            *(uint4*)(Bh + n * ARS + kq * 4) = hv;
            *(uint4*)(Bl + n * ARS + kq * 4) = lv;
        }
        // sweep: chunk outer, assigned pairs inner
        for (int chunk = 0; chunk < SS / CHUNK; chunk++) {
            for (int pair = blockIdx.x; pair < NSCAN; pair += NPROD) {
                long long s0 = (long long)chunk * CHUNK;
                prod_tile(usm, xg, pre, (long long)(2 * pair)     * SS + s0);
                prod_tile(usm, xg, pre, (long long)(2 * pair + 1) * SS + s0);
                __syncthreads();                       // all STG issued
                if (tid == 0) {
                    __threadfence();                   // release
                    g_flag[pair] = (chunk + 1) * CHUNK;
                }
            }
        }
        return;
    }

    // ================= scan CTA (round-7 body) =================
    float* sW = smem;                    // [256][PTS]
    float* hb = smem + SW_FLOATS;        // [2][2][HH]

    const int pair = blockIdx.x - NPROD;
    const int b0   = pair * 2;
    const int w  = tid >> 5;
    const int l  = tid & 31;
    const int c0 = 16 * l + 2 * w;
    const int c1 = c0 + 1;

    u64 wp0[REG_K / 2], wp1[REG_K / 2];
#pragma unroll
    for (int j = 0; j < REG_K / 2; j++) {
        wp0[j] = packf2(Rm[(2 * j) * GG + c0], Rm[(2 * j + 1) * GG + c0]);
        wp1[j] = packf2(Rm[(2 * j) * GG + c1], Rm[(2 * j + 1) * GG + c1]);
    }
    {
        float* slab = sW + tid * PTS;
#pragma unroll
        for (int kc = 0; kc < SMK; kc += 4) {
            int k = REG_K + kc;
            slab[kc * 2 + 0] = Rm[(k + 0) * GG + c0];
            slab[kc * 2 + 1] = Rm[(k + 1) * GG + c0];
            slab[kc * 2 + 2] = Rm[(k + 0) * GG + c1];
            slab[kc * 2 + 3] = Rm[(k + 1) * GG + c1];
            slab[kc * 2 + 4] = Rm[(k + 2) * GG + c0];
            slab[kc * 2 + 5] = Rm[(k + 3) * GG + c0];
            slab[kc * 2 + 6] = Rm[(k + 2) * GG + c1];
            slab[kc * 2 + 7] = Rm[(k + 3) * GG + c1];
        }
    }
    const float bg0 = bias[c0];
    const float bg1 = bias[c1];

    hb[tid] = 0.0f;
    hb[tid + 256] = 0.0f;
    __syncthreads();

    const float* pr0 = pre + (long long)(b0)     * SS * GG;
    const float* pr1 = pre + (long long)(b0 + 1) * SS * GG;

    int seen = 0;
#define WAITS(need) do { int _n = (need); if (seen < _n) {                      \
        while ((seen = g_flag[pair]) < _n) {}                                   \
        __threadfence(); } } while (0)

    WAITS(1);
    float2 p0 = *(const float2*)(pr0 + c0);
    float2 p1 = *(const float2*)(pr1 + c0);

    const int my_row = (l >> 4) & 1;
    const int my_hid = 16 * (l & 7) + 2 * w + ((l >> 3) & 1);
    float c_ = 0.0f, n_ = 0.0f, m_ = 0.0f;

    const bool lo16 = (l < 16);
    const bool b3   = ((l >> 3) & 1) != 0;
    const float* sWg = sW + tid * PTS;

#pragma unroll 1
    for (int step = 0; step < SS; step++) {
        const float* h0 = hb + (step & 1) * 256;
        const float* h1 = h0 + HH;
        float* hn = hb + ((step + 1) & 1) * 256;

        float2 q0 = make_float2(0.f, 0.f), q1 = make_float2(0.f, 0.f);
        if (step + 1 < SS) {
            WAITS(step + 2);
            long long off = (long long)(step + 1) * GG;
            q0 = *(const float2*)(pr0 + off + c0);
            q1 = *(const float2*)(pr1 + off + c0);
        }

        u64 a00 = 0, a10 = 0, a01 = 0, a11 = 0;

#pragma unroll
        for (int k = 0; k < REG_K; k += 4) {
            ulonglong2 hp0 = *(const ulonglong2*)(h0 + k);
            ulonglong2 hp1 = *(const ulonglong2*)(h1 + k);
            int j = k / 2;
            a00 = ffma2(hp0.x, wp0[j],     a00);
            a10 = ffma2(hp0.x, wp1[j],     a10);
            a01 = ffma2(hp1.x, wp0[j],     a01);
            a11 = ffma2(hp1.x, wp1[j],     a11);
            a00 = ffma2(hp0.y, wp0[j + 1], a00);
            a10 = ffma2(hp0.y, wp1[j + 1], a10);
            a01 = ffma2(hp1.y, wp0[j + 1], a01);
            a11 = ffma2(hp1.y, wp1[j + 1], a11);
        }
#pragma unroll
        for (int k = 0; k < SMK; k += 4) {
            ulonglong2 wv0 = *(const ulonglong2*)(sWg + k * 2);
            ulonglong2 wv1 = *(const ulonglong2*)(sWg + k * 2 + 4);
            ulonglong2 hp0 = *(const ulonglong2*)(h0 + REG_K + k);
            ulonglong2 hp1 = *(const ulonglong2*)(h1 + REG_K + k);
            a00 = ffma2(hp0.x, wv0.x, a00);
            a10 = ffma2(hp0.x, wv0.y, a10);
            a01 = ffma2(hp1.x, wv0.x, a01);
            a11 = ffma2(hp1.x, wv0.y, a11);
            a00 = ffma2(hp0.y, wv1.x, a00);
            a10 = ffma2(hp0.y, wv1.y, a10);
            a01 = ffma2(hp1.y, wv1.x, a01);
            a11 = ffma2(hp1.y, wv1.y, a11);
        }

        float2 t0 = unpackf2(a00), t1 = unpackf2(a10);
        float2 t2 = unpackf2(a01), t3 = unpackf2(a11);
        float aa = t0.x + t0.y + p0.x + bg0;
        float bb = t1.x + t1.y + p0.y + bg1;
        float cc = t2.x + t2.y + p1.x + bg0;
        float dd = t3.x + t3.y + p1.y + bg1;

        // warp-local gate transpose (4 shuffles)
        float u1 = lo16 ? cc : aa;
        float u2 = lo16 ? dd : bb;
        float r1v = __shfl_xor_sync(0xFFFFFFFFu, u1, 16);
        float r2v = __shfl_xor_sync(0xFFFFFFFFu, u2, 16);
        float Ag = lo16 ? aa : r1v;
        float Bg = lo16 ? bb : r2v;
        float Cg = lo16 ? r1v : cc;
        float Dg = lo16 ? r2v : dd;
        float s1in = b3 ? Ag : Bg;
        float s2in = b3 ? Cg : Dg;
        float e1 = __shfl_xor_sync(0xFFFFFFFFu, s1in, 8);
        float e2 = __shfl_xor_sync(0xFFFFFFFFu, s2in, 8);
        float iv = b3 ? e1 : Ag;
        float fv = b3 ? Bg : e1;
        float ov = b3 ? e2 : Cg;
        float zv = b3 ? Dg : e2;

        float tz = fast_tanh(zv);
        float so = __fdividef(1.0f, 1.0f + __expf(-ov));
        float lf = fminf(fv, 0.0f) - __logf(1.0f + __expf(-fabsf(fv)));
        float mn = fmaxf(lf + m_, iv);
        float ip = __expf(iv - mn);
        float fp = __expf(lf + m_ - mn);
        c_ = fp * c_ + ip * tz;
        n_ = fp * n_ + ip;
        m_ = mn;
        float hv = so * fast_tanh(__fdividef(c_, n_));

        hn[my_row * HH + my_hid] = hv;
        out[((long long)(b0 + my_row) * SS + step) * HH + my_hid] = hv;

        p0 = q0; p1 = q1;
        __syncthreads();
    }
}

extern "C" void kernel_launch(void* const* d_in, const int* in_sizes, int n_in,
                              void* d_out, int out_size)
{
    const float* xg = (const float*)d_in[0];
    const float* Wm = (const float*)d_in[1];
    const float* Rm = (const float*)d_in[2];
    const float* bv = (const float*)d_in[3];
    if (n_in >= 3 && in_sizes[1] == HH * GG && in_sizes[2] == GG * II) {
        const float* t = Wm; Wm = Rm; Rm = t;
    }
    float* out = (float*)d_out;

    float* pre = nullptr;
    cudaGetSymbolAddress((void**)&pre, g_pre);

    cudaFuncSetAttribute(slstm_combined_kernel,
                         cudaFuncAttributeMaxDynamicSharedMemorySize, SMEM_BYTES);

    prep_w_kernel<<<64, 256>>>(Wm);
    slstm_combined_kernel<<<NPROD + NSCAN, NTHR, SMEM_BYTES>>>(xg, Rm, bv, pre, out);
}